// round 4
// baseline (speedup 1.0000x reference)
#include <cuda_runtime.h>
#include <math.h>

typedef unsigned long long u64;
#define SROW 12            // k-major row stride in floats (48B: 16B-aligned, bank-spread)
#define SROWB 48           // bytes

// ---- packed f32x2 primitives (sm_100+; ptxas never auto-fuses these from C++) ----
static __device__ __forceinline__ u64 pack2(float x) {
    u64 r; asm("mov.b64 %0, {%1, %1};" : "=l"(r) : "f"(x)); return r;
}
static __device__ __forceinline__ void fma2(u64& d, u64 a, u64 b) {
    asm("fma.rn.f32x2 %0, %1, %2, %0;" : "+l"(d) : "l"(a), "l"(b));
}
static __device__ __forceinline__ void add2(u64& d, u64 a) {
    asm("add.rn.f32x2 %0, %0, %1;" : "+l"(d) : "l"(a));
}
static __device__ __forceinline__ float2 unpack2(u64 x) {
    float lo, hi; asm("mov.b64 {%0, %1}, %2;" : "=f"(lo), "=f"(hi) : "l"(x));
    return make_float2(lo, hi);
}
// 16B shared load, 32-bit shared-window address (guaranteed LDS.128)
static __device__ __forceinline__ void lds128(u64& a, u64& b, unsigned addr) {
    asm volatile("ld.shared.v2.u64 {%0, %1}, [%2];" : "=l"(a), "=l"(b) : "r"(addr));
}

// flag-independent transcendentals (MUFU EX2/RCP based, rel err ~1e-6; immune to
// whether the harness compiles with --use_fast_math)
static __device__ __forceinline__ float fast_tanh(float x) {
    float xc = fminf(fmaxf(x, -9.0f), 9.0f);
    float e = __expf(2.0f * xc);
    return (e - 1.0f) * __frcp_rn(e + 1.0f);
}
static __device__ __forceinline__ float fast_sigm(float x) {
    float xc = fminf(fmaxf(x, -30.0f), 30.0f);
    return __frcp_rn(1.0f + __expf(-xc));
}

struct Seg { unsigned off; int K; };   // off = 32-bit shared-window byte address

// out[8 rows][256 cols] = epi(sum_segs inT @ W + bias)
// 256 threads: tid<128 low K half, tid>=128 high K half; each weight element is
// read exactly once per CTA. inT k-major [K][SROW] in SMEM; all lanes of a warp
// read the same SMEM address -> broadcast, conflict-free.
template <class Epi>
static __device__ __forceinline__ void gemm256(
    const float* __restrict__ W, int ldW, const float* __restrict__ bias,
    const Seg* segs, int nseg, int Ktot, u64* red, int tid, Epi epi)
{
    const int Kh = Ktot >> 1;
    const int g = tid >> 7, j = tid & 127, n0 = j * 2;
    const int lo = g * Kh, hi = lo + Kh;
    const int ldW2 = ldW >> 1;
    u64 acc[2][4];
    #pragma unroll
    for (int c = 0; c < 2; ++c)
        #pragma unroll
        for (int p = 0; p < 4; ++p) acc[c][p] = 0ull;

    int base = 0;
    for (int s = 0; s < nseg; ++s) {
        int K = segs[s].K;
        int a = lo - base; if (a < 0) a = 0;
        int b = hi - base; if (b > K) b = K;
        if (a < b) {
            const float2* wrow = (const float2*)(W + (size_t)(base + a) * ldW) + (n0 >> 1);
            unsigned ip = segs[s].off + (unsigned)a * SROWB;
            #pragma unroll 16
            for (int k = a; k < b; ++k) {
                float2 wv = __ldg(wrow);
                u64 iax, iay, ibx, iby;
                lds128(iax, iay, ip);
                lds128(ibx, iby, ip + 16);
                u64 w0 = pack2(wv.x), w1 = pack2(wv.y);
                fma2(acc[0][0], iax, w0); fma2(acc[0][1], iay, w0);
                fma2(acc[0][2], ibx, w0); fma2(acc[0][3], iby, w0);
                fma2(acc[1][0], iax, w1); fma2(acc[1][1], iay, w1);
                fma2(acc[1][2], ibx, w1); fma2(acc[1][3], iby, w1);
                wrow += ldW2; ip += SROWB;
            }
        }
        base += K;
    }
    if (g) {
        #pragma unroll
        for (int c = 0; c < 2; ++c)
            #pragma unroll
            for (int p = 0; p < 4; ++p) red[j * 9 + c * 4 + p] = acc[c][p];
    }
    __syncthreads();
    if (!g) {
        #pragma unroll
        for (int c = 0; c < 2; ++c) {
            float v[8];
            #pragma unroll
            for (int p = 0; p < 4; ++p) {
                add2(acc[c][p], red[j * 9 + c * 4 + p]);
                float2 f = unpack2(acc[c][p]);
                v[2 * p] = f.x; v[2 * p + 1] = f.y;
            }
            float bn = __ldg(bias + n0 + c);
            #pragma unroll
            for (int r = 0; r < 8; ++r) v[r] += bn;
            epi(n0 + c, v);
        }
    }
    __syncthreads();
}

// N=64 output head: 1 col/thread, 4-way K split.
template <class Epi>
static __device__ __forceinline__ void gemm64(
    const float* __restrict__ W, int ldW, const float* __restrict__ bias,
    unsigned in_off, int Ktot, u64* red, int tid, Epi epi)
{
    const int Kq = Ktot >> 2;
    const int g = tid >> 6, j = tid & 63;
    u64 acc[4] = {0ull, 0ull, 0ull, 0ull};
    const float* wrow = W + (size_t)(g * Kq) * ldW + j;
    unsigned ip = in_off + (unsigned)(g * Kq) * SROWB;
    #pragma unroll 16
    for (int k = 0; k < Kq; ++k) {
        float wv = __ldg(wrow);
        u64 iax, iay, ibx, iby;
        lds128(iax, iay, ip);
        lds128(ibx, iby, ip + 16);
        u64 w0 = pack2(wv);
        fma2(acc[0], iax, w0); fma2(acc[1], iay, w0);
        fma2(acc[2], ibx, w0); fma2(acc[3], iby, w0);
        wrow += ldW; ip += SROWB;
    }
    if (g) {
        #pragma unroll
        for (int p = 0; p < 4; ++p) red[((g - 1) * 64 + j) * 4 + p] = acc[p];
    }
    __syncthreads();
    if (!g) {
        #pragma unroll
        for (int gg = 1; gg < 4; ++gg)
            #pragma unroll
            for (int p = 0; p < 4; ++p) add2(acc[p], red[((gg - 1) * 64 + j) * 4 + p]);
        float v[8];
        #pragma unroll
        for (int p = 0; p < 4; ++p) {
            float2 f = unpack2(acc[p]);
            v[2 * p] = f.x; v[2 * p + 1] = f.y;
        }
        float bn = __ldg(bias + j);
        #pragma unroll
        for (int r = 0; r < 8; ++r) v[r] += bn;
        epi(j, v);
    }
    __syncthreads();
}

// ---- SMEM layout (float offsets) ----
#define O_HI    0
#define O_STD   3072
#define O_ODE   6144
#define O_T1    9216
#define O_U     12288
#define O_R     15360
#define O_ODER  18432
#define O_STDR  21504
#define O_X     24576   // 64*SROW = 768
#define O_RED   25344   // 2304 floats (>= 1152 u64)
#define O_TIME  27648   // float xtime[200]
#define O_INT   27848   // int invx[200], invy[200]
#define SMEM_BYTES ((27848 + 400) * 4)

__global__ void __launch_bounds__(256, 1) recur_kernel(
    const float* __restrict__ xd, const float* __restrict__ xm,
    const float* __restrict__ xt,
    const int* __restrict__ xti, const int* __restrict__ yti,
    const float* __restrict__ ugw1, const float* __restrict__ ugb1,
    const float* __restrict__ ugw2, const float* __restrict__ ugb2,
    const float* __restrict__ rgw1, const float* __restrict__ rgb1,
    const float* __restrict__ rgw2, const float* __restrict__ rgb2,
    const float* __restrict__ nsw1, const float* __restrict__ nsb1,
    const float* __restrict__ nsw2, const float* __restrict__ nsb2,
    const float* __restrict__ ow1, const float* __restrict__ ob1,
    const float* __restrict__ ow2, const float* __restrict__ ob2,
    const float* __restrict__ fw1, const float* __restrict__ fb1,
    const float* __restrict__ fw2, const float* __restrict__ fb2,
    float* __restrict__ out)
{
    extern __shared__ float sm[];
    const unsigned SB = (unsigned)__cvta_generic_to_shared(sm);
    float* s_hi   = sm + O_HI;
    float* s_std  = sm + O_STD;
    float* s_ode  = sm + O_ODE;
    float* s_t1   = sm + O_T1;
    float* s_u    = sm + O_U;
    float* s_r    = sm + O_R;
    float* s_x    = sm + O_X;
    u64*   s_red  = (u64*)(sm + O_RED);
    float* s_time = sm + O_TIME;
    int*   s_invx = (int*)(sm + O_INT);
    int*   s_invy = s_invx + 200;

    const unsigned u_hi   = SB + O_HI * 4;
    const unsigned u_std  = SB + O_STD * 4;
    const unsigned u_ode  = SB + O_ODE * 4;
    const unsigned u_t1   = SB + O_T1 * 4;
    const unsigned u_oder = SB + O_ODER * 4;
    const unsigned u_stdr = SB + O_STDR * 4;
    const unsigned u_x    = SB + O_X * 4;

    const int tid = threadIdx.x;
    const int b0 = blockIdx.x * 8;

    for (int i = tid; i < 3072; i += 256) { s_hi[i] = 0.0f; s_std[i] = 0.0f; }
    if (tid < 200) { s_invx[tid] = -1; s_invy[tid] = -1; s_time[tid] = __ldg(xt + tid); }
    __syncthreads();
    if (tid < 190) s_invx[xti[tid]] = tid;
    if (tid < 50)  s_invy[yti[tid]] = tid;
    __syncthreads();

    const float xlast = s_time[199];

    auto epiTanhT1 = [&](int n, const float* v) {
        #pragma unroll
        for (int r = 0; r < 8; ++r) s_t1[n * SROW + r] = fast_tanh(v[r]);
    };

    for (int t = 0; t < 200; ++t) {
        // scatter this step's observation slot into s_x (zeros if unobserved)
        {
            int jx = s_invx[t];
            #pragma unroll
            for (int idx = tid; idx < 512; idx += 256) {
                int r = idx >> 6, c = idx & 63;
                float v = 0.0f;
                if (jx >= 0) {
                    size_t off = ((size_t)(b0 + r) * 190 + jx) * 64 + c;
                    v = __ldg(xd + off) * __ldg(xm + off);
                }
                s_x[c * SROW + r] = v;   // first read happens 2+ __syncthreads later
            }
        }
        // dt exactly as the reference's carried (prev_ti, ti) produce it
        float dt;
        if (t == 0)      dt = -0.01f;
        else if (t == 1) dt = xlast - s_time[0];
        else             dt = s_time[t - 2] - s_time[t - 1];

        Seg sH[1]  = {{u_hi, 256}};
        Seg sT[1]  = {{u_t1, 256}};
        Seg sYC[3] = {{u_ode, 256}, {u_std, 256}, {u_x, 64}};
        Seg sCC[3] = {{u_oder, 256}, {u_stdr, 256}, {u_x, 64}};

        // f = MLP(hi); hi_ode = hi + f*dt
        gemm256(fw1, 256, fb1, sH, 1, 256, s_red, tid, epiTanhT1);
        gemm256(fw2, 256, fb2, sT, 1, 256, s_red, tid,
            [&](int n, const float* v) {
                #pragma unroll
                for (int r = 0; r < 8; ++r)
                    s_ode[n * SROW + r] = s_hi[n * SROW + r] + v[r] * dt;
            });
        // u = sigmoid(MLP(yc))
        gemm256(ugw1, 256, ugb1, sYC, 3, 576, s_red, tid, epiTanhT1);
        gemm256(ugw2, 256, ugb2, sT, 1, 256, s_red, tid,
            [&](int n, const float* v) {
                #pragma unroll
                for (int r = 0; r < 8; ++r) s_u[n * SROW + r] = fast_sigm(v[r]);
            });
        // r = sigmoid(MLP(yc))
        gemm256(rgw1, 256, rgb1, sYC, 3, 576, s_red, tid, epiTanhT1);
        gemm256(rgw2, 256, rgb2, sT, 1, 256, s_red, tid,
            [&](int n, const float* v) {
                #pragma unroll
                for (int r = 0; r < 8; ++r) s_r[n * SROW + r] = fast_sigm(v[r]);
            });
        // cc pieces: ode*r, std*r (one column per thread)
        {
            float* oderp = sm + O_ODER;
            float* stdrp = sm + O_STDR;
            int n = tid;
            #pragma unroll
            for (int h = 0; h < 2; ++h) {
                float4 rr = *(const float4*)(s_r   + n * SROW + 4 * h);
                float4 oo = *(const float4*)(s_ode + n * SROW + 4 * h);
                float4 dd = *(const float4*)(s_std + n * SROW + 4 * h);
                *(float4*)(oderp + n * SROW + 4 * h) =
                    make_float4(oo.x*rr.x, oo.y*rr.y, oo.z*rr.z, oo.w*rr.w);
                *(float4*)(stdrp + n * SROW + 4 * h) =
                    make_float4(dd.x*rr.x, dd.y*rr.y, dd.z*rr.z, dd.w*rr.w);
            }
        }
        __syncthreads();
        // ns = MLP(cc): hidden, then the two N=256 halves of nsw2 [256][512]
        gemm256(nsw1, 256, nsb1, sCC, 3, 576, s_red, tid, epiTanhT1);
        gemm256(nsw2, 512, nsb2, sT, 1, 256, s_red, tid,
            [&](int n, const float* v) {   // new_y -> s_hi
                #pragma unroll
                for (int r = 0; r < 8; ++r) {
                    float u = s_u[n * SROW + r];
                    s_hi[n * SROW + r] = (1.0f - u) * v[r] + u * s_ode[n * SROW + r];
                }
            });
        gemm256(nsw2 + 256, 512, nsb2 + 256, sT, 1, 256, s_red, tid,
            [&](int n, const float* v) {   // new_y_std -> s_std
                #pragma unroll
                for (int r = 0; r < 8; ++r) {
                    float u = s_u[n * SROW + r];
                    float nss = fabsf(v[r]);
                    s_std[n * SROW + r] =
                        fabsf((1.0f - u) * nss + u * s_std[n * SROW + r]);
                }
            });
        // output head only on the 50 sampled steps
        int q = s_invy[t];
        if (q >= 0) {
            Seg sHn[1] = {{u_hi, 256}};
            gemm256(ow1, 256, ob1, sHn, 1, 256, s_red, tid, epiTanhT1);
            gemm64(ow2, 64, ob2, u_t1, 256, s_red, tid,
                [&](int n, const float* v) {
                    #pragma unroll
                    for (int r = 0; r < 8; ++r)
                        out[((size_t)(b0 + r) * 50 + q) * 64 + n] = v[r];
                });
        }
    }
}

extern "C" void kernel_launch(void* const* d_in, const int* in_sizes, int n_in,
                              void* d_out, int out_size) {
    (void)in_sizes; (void)n_in; (void)out_size;
    const float* xd   = (const float*)d_in[0];
    const float* xm   = (const float*)d_in[1];
    const float* xt   = (const float*)d_in[2];
    const int*   xti  = (const int*)d_in[3];
    const int*   yti  = (const int*)d_in[4];
    const float* ugw1 = (const float*)d_in[5];
    const float* ugb1 = (const float*)d_in[6];
    const float* ugw2 = (const float*)d_in[7];
    const float* ugb2 = (const float*)d_in[8];
    const float* rgw1 = (const float*)d_in[9];
    const float* rgb1 = (const float*)d_in[10];
    const float* rgw2 = (const float*)d_in[11];
    const float* rgb2 = (const float*)d_in[12];
    const float* nsw1 = (const float*)d_in[13];
    const float* nsb1 = (const float*)d_in[14];
    const float* nsw2 = (const float*)d_in[15];
    const float* nsb2 = (const float*)d_in[16];
    const float* ow1  = (const float*)d_in[17];
    const float* ob1  = (const float*)d_in[18];
    const float* ow2  = (const float*)d_in[19];
    const float* ob2  = (const float*)d_in[20];
    const float* fw1  = (const float*)d_in[21];
    const float* fb1  = (const float*)d_in[22];
    const float* fw2  = (const float*)d_in[23];
    const float* fb2  = (const float*)d_in[24];

    cudaFuncSetAttribute(recur_kernel,
                         cudaFuncAttributeMaxDynamicSharedMemorySize, SMEM_BYTES);
    recur_kernel<<<128, 256, SMEM_BYTES>>>(
        xd, xm, xt, xti, yti,
        ugw1, ugb1, ugw2, ugb2,
        rgw1, rgb1, rgw2, rgb2,
        nsw1, nsb1, nsw2, nsb2,
        ow1, ob1, ow2, ob2,
        fw1, fb1, fw2, fb2,
        (float*)d_out);
}

// round 8
// speedup vs baseline: 1.6547x; 1.6547x over previous
#include <cuda_runtime.h>
#include <math.h>

typedef unsigned long long u64;
#define SROW 12            // k-major row stride in floats (48B: 16B-aligned, bank-spread)
#define SROWB 48           // bytes
#define NTHR 512

// ---- packed f32x2 primitives (sm_100+; ptxas never auto-fuses these from C++) ----
static __device__ __forceinline__ u64 pack2(float x) {
    u64 r; asm("mov.b64 %0, {%1, %1};" : "=l"(r) : "f"(x)); return r;
}
static __device__ __forceinline__ void fma2(u64& d, u64 a, u64 b) {
    asm("fma.rn.f32x2 %0, %1, %2, %0;" : "+l"(d) : "l"(a), "l"(b));
}
static __device__ __forceinline__ void add2(u64& d, u64 a) {
    asm("add.rn.f32x2 %0, %0, %1;" : "+l"(d) : "l"(a));
}
static __device__ __forceinline__ float2 unpack2(u64 x) {
    float lo, hi; asm("mov.b64 {%0, %1}, %2;" : "=f"(lo), "=f"(hi) : "l"(x));
    return make_float2(lo, hi);
}
// 16B shared load/store, 32-bit shared-window address (guaranteed LDS/STS.128)
static __device__ __forceinline__ void lds128(u64& a, u64& b, unsigned addr) {
    asm volatile("ld.shared.v2.u64 {%0, %1}, [%2];" : "=l"(a), "=l"(b) : "r"(addr));
}
static __device__ __forceinline__ void sts128(unsigned addr, u64 a, u64 b) {
    asm volatile("st.shared.v2.u64 [%0], {%1, %2};" :: "r"(addr), "l"(a), "l"(b) : "memory");
}

// flag-independent transcendentals (MUFU EX2/RCP based, rel err ~1e-6)
static __device__ __forceinline__ float fast_tanh(float x) {
    float xc = fminf(fmaxf(x, -9.0f), 9.0f);
    float e = __expf(2.0f * xc);
    return (e - 1.0f) * __frcp_rn(e + 1.0f);
}
static __device__ __forceinline__ float fast_sigm(float x) {
    float xc = fminf(fmaxf(x, -30.0f), 30.0f);
    return __frcp_rn(1.0f + __expf(-xc));
}

struct Seg { unsigned off; int K; };   // off = 32-bit shared-window byte address

// out[8 rows][256 cols] = epi(sum_segs inT @ W + bias)
// 512 threads, 4-way K-split: g = tid>>7 owns a K-quarter, j = tid&127 a col pair.
// Each weight element read exactly once per CTA. inT k-major [K][SROW] in SMEM;
// all lanes of a warp read the same SMEM address -> broadcast, conflict-free.
template <class Epi>
static __device__ __forceinline__ void gemm256(
    const float* __restrict__ W, int ldW, const float* __restrict__ bias,
    const Seg* segs, int nseg, int Ktot, unsigned red_off, int tid, Epi epi)
{
    const int Kq = Ktot >> 2;
    const int g = tid >> 7, j = tid & 127, n0 = j * 2;
    const int lo = g * Kq, hi = lo + Kq;
    const int ldW2 = ldW >> 1;
    u64 acc[2][4];
    #pragma unroll
    for (int c = 0; c < 2; ++c)
        #pragma unroll
        for (int p = 0; p < 4; ++p) acc[c][p] = 0ull;

    int base = 0;
    for (int s = 0; s < nseg; ++s) {
        int K = segs[s].K;
        int a = lo - base; if (a < 0) a = 0;
        int b = hi - base; if (b > K) b = K;
        if (a < b) {
            const float2* wrow = (const float2*)(W + (size_t)(base + a) * ldW) + (n0 >> 1);
            unsigned ip = segs[s].off + (unsigned)a * SROWB;
            #pragma unroll 8
            for (int k = a; k < b; ++k) {
                float2 wv = __ldg(wrow);
                u64 iax, iay, ibx, iby;
                lds128(iax, iay, ip);
                lds128(ibx, iby, ip + 16);
                u64 w0 = pack2(wv.x), w1 = pack2(wv.y);
                fma2(acc[0][0], iax, w0); fma2(acc[0][1], iay, w0);
                fma2(acc[0][2], ibx, w0); fma2(acc[0][3], iby, w0);
                fma2(acc[1][0], iax, w1); fma2(acc[1][1], iay, w1);
                fma2(acc[1][2], ibx, w1); fma2(acc[1][3], iby, w1);
                wrow += ldW2; ip += SROWB;
            }
        }
        base += K;
    }
    if (g) {
        unsigned wp = red_off + (unsigned)(((g - 1) * 128 + j) * 8) * 8;
        #pragma unroll
        for (int c = 0; c < 2; ++c)
            #pragma unroll
            for (int p = 0; p < 4; p += 2)
                sts128(wp + (unsigned)(c * 4 + p) * 8, acc[c][p], acc[c][p + 1]);
    }
    __syncthreads();
    if (!g) {
        #pragma unroll
        for (int c = 0; c < 2; ++c) {
            float v[8];
            #pragma unroll
            for (int p = 0; p < 4; p += 2) {
                #pragma unroll
                for (int gg = 0; gg < 3; ++gg) {
                    u64 ra, rb;
                    lds128(ra, rb, red_off + (unsigned)((gg * 128 + j) * 8 + c * 4 + p) * 8);
                    add2(acc[c][p], ra); add2(acc[c][p + 1], rb);
                }
            }
            #pragma unroll
            for (int p = 0; p < 4; ++p) {
                float2 f = unpack2(acc[c][p]);
                v[2 * p] = f.x; v[2 * p + 1] = f.y;
            }
            float bn = __ldg(bias + n0 + c);
            #pragma unroll
            for (int r = 0; r < 8; ++r) v[r] += bn;
            epi(n0 + c, v);
        }
    }
    __syncthreads();
}

// N=64 output head: 1 col/thread, 8-way K split.
template <class Epi>
static __device__ __forceinline__ void gemm64(
    const float* __restrict__ W, int ldW, const float* __restrict__ bias,
    unsigned in_off, int Ktot, unsigned red_off, int tid, Epi epi)
{
    const int Kq = Ktot >> 3;
    const int g = tid >> 6, j = tid & 63;
    u64 acc[4] = {0ull, 0ull, 0ull, 0ull};
    const float* wrow = W + (size_t)(g * Kq) * ldW + j;
    unsigned ip = in_off + (unsigned)(g * Kq) * SROWB;
    #pragma unroll 8
    for (int k = 0; k < Kq; ++k) {
        float wv = __ldg(wrow);
        u64 iax, iay, ibx, iby;
        lds128(iax, iay, ip);
        lds128(ibx, iby, ip + 16);
        u64 w0 = pack2(wv);
        fma2(acc[0], iax, w0); fma2(acc[1], iay, w0);
        fma2(acc[2], ibx, w0); fma2(acc[3], iby, w0);
        wrow += ldW; ip += SROWB;
    }
    if (g) {
        unsigned wp = red_off + (unsigned)(((g - 1) * 64 + j) * 4) * 8;
        sts128(wp, acc[0], acc[1]);
        sts128(wp + 16, acc[2], acc[3]);
    }
    __syncthreads();
    if (!g) {
        #pragma unroll
        for (int gg = 0; gg < 7; ++gg) {
            u64 ra, rb, rc, rd;
            unsigned rp = red_off + (unsigned)((gg * 64 + j) * 4) * 8;
            lds128(ra, rb, rp);
            lds128(rc, rd, rp + 16);
            add2(acc[0], ra); add2(acc[1], rb);
            add2(acc[2], rc); add2(acc[3], rd);
        }
        float v[8];
        #pragma unroll
        for (int p = 0; p < 4; ++p) {
            float2 f = unpack2(acc[p]);
            v[2 * p] = f.x; v[2 * p + 1] = f.y;
        }
        float bn = __ldg(bias + j);
        #pragma unroll
        for (int r = 0; r < 8; ++r) v[r] += bn;
        epi(j, v);
    }
    __syncthreads();
}

// ---- SMEM layout (float offsets) ----
#define O_HI    0
#define O_STD   3072
#define O_ODE   6144
#define O_T1    9216
#define O_U     12288
#define O_R     15360
#define O_ODER  18432
#define O_STDR  21504
#define O_X     24576   // 64*SROW = 768
#define O_RED   25344   // 3072 u64 = 6144 floats
#define O_TIME  31488   // float xtime[200]
#define O_INT   31688   // int invx[200], invy[200]
#define SMEM_BYTES ((31688 + 400) * 4)

__global__ void __launch_bounds__(NTHR, 1) recur_kernel(
    const float* __restrict__ xd, const float* __restrict__ xm,
    const float* __restrict__ xt,
    const int* __restrict__ xti, const int* __restrict__ yti,
    const float* __restrict__ ugw1, const float* __restrict__ ugb1,
    const float* __restrict__ ugw2, const float* __restrict__ ugb2,
    const float* __restrict__ rgw1, const float* __restrict__ rgb1,
    const float* __restrict__ rgw2, const float* __restrict__ rgb2,
    const float* __restrict__ nsw1, const float* __restrict__ nsb1,
    const float* __restrict__ nsw2, const float* __restrict__ nsb2,
    const float* __restrict__ ow1, const float* __restrict__ ob1,
    const float* __restrict__ ow2, const float* __restrict__ ob2,
    const float* __restrict__ fw1, const float* __restrict__ fb1,
    const float* __restrict__ fw2, const float* __restrict__ fb2,
    float* __restrict__ out)
{
    extern __shared__ float sm[];
    const unsigned SB = (unsigned)__cvta_generic_to_shared(sm);
    float* s_hi   = sm + O_HI;
    float* s_std  = sm + O_STD;
    float* s_ode  = sm + O_ODE;
    float* s_t1   = sm + O_T1;
    float* s_u    = sm + O_U;
    float* s_r    = sm + O_R;
    float* s_x    = sm + O_X;
    float* s_time = sm + O_TIME;
    int*   s_invx = (int*)(sm + O_INT);
    int*   s_invy = s_invx + 200;

    const unsigned u_hi   = SB + O_HI * 4;
    const unsigned u_ode  = SB + O_ODE * 4;
    const unsigned u_std  = SB + O_STD * 4;
    const unsigned u_t1   = SB + O_T1 * 4;
    const unsigned u_oder = SB + O_ODER * 4;
    const unsigned u_stdr = SB + O_STDR * 4;
    const unsigned u_x    = SB + O_X * 4;
    const unsigned u_red  = SB + O_RED * 4;

    const int tid = threadIdx.x;
    const int b0 = blockIdx.x * 8;

    for (int i = tid; i < 3072; i += NTHR) { s_hi[i] = 0.0f; s_std[i] = 0.0f; }
    if (tid < 200) { s_invx[tid] = -1; s_invy[tid] = -1; s_time[tid] = __ldg(xt + tid); }
    __syncthreads();
    if (tid < 190) s_invx[xti[tid]] = tid;
    if (tid < 50)  s_invy[yti[tid]] = tid;
    __syncthreads();

    const float xlast = s_time[199];

    auto epiTanhT1 = [&](int n, const float* v) {
        #pragma unroll
        for (int r = 0; r < 8; ++r) s_t1[n * SROW + r] = fast_tanh(v[r]);
    };

    for (int t = 0; t < 200; ++t) {
        // scatter this step's observation slot into s_x (zeros if unobserved)
        {
            int jx = s_invx[t];
            int r = tid >> 6, c = tid & 63;   // 512 threads cover 8x64
            float v = 0.0f;
            if (jx >= 0) {
                size_t off = ((size_t)(b0 + r) * 190 + jx) * 64 + c;
                v = __ldg(xd + off) * __ldg(xm + off);
            }
            s_x[c * SROW + r] = v;   // first read happens 2+ __syncthreads later
        }
        // dt exactly as the reference's carried (prev_ti, ti) produce it
        float dt;
        if (t == 0)      dt = -0.01f;
        else if (t == 1) dt = xlast - s_time[0];
        else             dt = s_time[t - 2] - s_time[t - 1];

        Seg sH[1]  = {{u_hi, 256}};
        Seg sT[1]  = {{u_t1, 256}};
        Seg sYC[3] = {{u_ode, 256}, {u_std, 256}, {u_x, 64}};
        Seg sCC[3] = {{u_oder, 256}, {u_stdr, 256}, {u_x, 64}};

        // f = MLP(hi); hi_ode = hi + f*dt
        gemm256(fw1, 256, fb1, sH, 1, 256, u_red, tid, epiTanhT1);
        gemm256(fw2, 256, fb2, sT, 1, 256, u_red, tid,
            [&](int n, const float* v) {
                #pragma unroll
                for (int r = 0; r < 8; ++r)
                    s_ode[n * SROW + r] = s_hi[n * SROW + r] + v[r] * dt;
            });
        // u = sigmoid(MLP(yc))
        gemm256(ugw1, 256, ugb1, sYC, 3, 576, u_red, tid, epiTanhT1);
        gemm256(ugw2, 256, ugb2, sT, 1, 256, u_red, tid,
            [&](int n, const float* v) {
                #pragma unroll
                for (int r = 0; r < 8; ++r) s_u[n * SROW + r] = fast_sigm(v[r]);
            });
        // r = sigmoid(MLP(yc))
        gemm256(rgw1, 256, rgb1, sYC, 3, 576, u_red, tid, epiTanhT1);
        gemm256(rgw2, 256, rgb2, sT, 1, 256, u_red, tid,
            [&](int n, const float* v) {
                #pragma unroll
                for (int r = 0; r < 8; ++r) s_r[n * SROW + r] = fast_sigm(v[r]);
            });
        // cc pieces: ode*r, std*r (one column per thread, 256 active)
        if (tid < 256) {
            float* oderp = sm + O_ODER;
            float* stdrp = sm + O_STDR;
            int n = tid;
            #pragma unroll
            for (int h = 0; h < 2; ++h) {
                float4 rr = *(const float4*)(s_r   + n * SROW + 4 * h);
                float4 oo = *(const float4*)(s_ode + n * SROW + 4 * h);
                float4 dd = *(const float4*)(s_std + n * SROW + 4 * h);
                *(float4*)(oderp + n * SROW + 4 * h) =
                    make_float4(oo.x*rr.x, oo.y*rr.y, oo.z*rr.z, oo.w*rr.w);
                *(float4*)(stdrp + n * SROW + 4 * h) =
                    make_float4(dd.x*rr.x, dd.y*rr.y, dd.z*rr.z, dd.w*rr.w);
            }
        }
        __syncthreads();
        // ns = MLP(cc): hidden, then the two N=256 halves of nsw2 [256][512]
        gemm256(nsw1, 256, nsb1, sCC, 3, 576, u_red, tid, epiTanhT1);
        gemm256(nsw2, 512, nsb2, sT, 1, 256, u_red, tid,
            [&](int n, const float* v) {   // new_y -> s_hi
                #pragma unroll
                for (int r = 0; r < 8; ++r) {
                    float u = s_u[n * SROW + r];
                    s_hi[n * SROW + r] = (1.0f - u) * v[r] + u * s_ode[n * SROW + r];
                }
            });
        gemm256(nsw2 + 256, 512, nsb2 + 256, sT, 1, 256, u_red, tid,
            [&](int n, const float* v) {   // new_y_std -> s_std
                #pragma unroll
                for (int r = 0; r < 8; ++r) {
                    float u = s_u[n * SROW + r];
                    float nss = fabsf(v[r]);
                    s_std[n * SROW + r] =
                        fabsf((1.0f - u) * nss + u * s_std[n * SROW + r]);
                }
            });
        // output head only on the 50 sampled steps
        int q = s_invy[t];
        if (q >= 0) {
            Seg sHn[1] = {{u_hi, 256}};
            gemm256(ow1, 256, ob1, sHn, 1, 256, u_red, tid, epiTanhT1);
            gemm64(ow2, 64, ob2, u_t1, 256, u_red, tid,
                [&](int n, const float* v) {
                    #pragma unroll
                    for (int r = 0; r < 8; ++r)
                        out[((size_t)(b0 + r) * 50 + q) * 64 + n] = v[r];
                });
        }
    }
}

extern "C" void kernel_launch(void* const* d_in, const int* in_sizes, int n_in,
                              void* d_out, int out_size) {
    (void)in_sizes; (void)n_in; (void)out_size;
    const float* xd   = (const float*)d_in[0];
    const float* xm   = (const float*)d_in[1];
    const float* xt   = (const float*)d_in[2];
    const int*   xti  = (const int*)d_in[3];
    const int*   yti  = (const int*)d_in[4];
    const float* ugw1 = (const float*)d_in[5];
    const float* ugb1 = (const float*)d_in[6];
    const float* ugw2 = (const float*)d_in[7];
    const float* ugb2 = (const float*)d_in[8];
    const float* rgw1 = (const float*)d_in[9];
    const float* rgb1 = (const float*)d_in[10];
    const float* rgw2 = (const float*)d_in[11];
    const float* rgb2 = (const float*)d_in[12];
    const float* nsw1 = (const float*)d_in[13];
    const float* nsb1 = (const float*)d_in[14];
    const float* nsw2 = (const float*)d_in[15];
    const float* nsb2 = (const float*)d_in[16];
    const float* ow1  = (const float*)d_in[17];
    const float* ob1  = (const float*)d_in[18];
    const float* ow2  = (const float*)d_in[19];
    const float* ob2  = (const float*)d_in[20];
    const float* fw1  = (const float*)d_in[21];
    const float* fb1  = (const float*)d_in[22];
    const float* fw2  = (const float*)d_in[23];
    const float* fb2  = (const float*)d_in[24];

    cudaFuncSetAttribute(recur_kernel,
                         cudaFuncAttributeMaxDynamicSharedMemorySize, SMEM_BYTES);
    recur_kernel<<<128, NTHR, SMEM_BYTES>>>(
        xd, xm, xt, xti, yti,
        ugw1, ugb1, ugw2, ugb2,
        rgw1, rgb1, rgw2, rgb2,
        nsw1, nsb1, nsw2, nsb2,
        ow1, ob1, ow2, ob2,
        fw1, fb1, fw2, fb2,
        (float*)d_out);
}

// round 10
// speedup vs baseline: 1.6572x; 1.0016x over previous
#include <cuda_runtime.h>
#include <math.h>

typedef unsigned long long u64;
#define SROW 12            // k-major row stride in floats (48B: 16B-aligned, bank-spread)
#define SROWB 48           // bytes
#define NTHR 512

// ---- packed f32x2 primitives (sm_100+; ptxas never auto-fuses these from C++) ----
static __device__ __forceinline__ u64 pack2(float x) {
    u64 r; asm("mov.b64 %0, {%1, %1};" : "=l"(r) : "f"(x)); return r;
}
static __device__ __forceinline__ void fma2(u64& d, u64 a, u64 b) {
    asm("fma.rn.f32x2 %0, %1, %2, %0;" : "+l"(d) : "l"(a), "l"(b));
}
static __device__ __forceinline__ void add2(u64& d, u64 a) {
    asm("add.rn.f32x2 %0, %0, %1;" : "+l"(d) : "l"(a));
}
static __device__ __forceinline__ float2 unpack2(u64 x) {
    float lo, hi; asm("mov.b64 {%0, %1}, %2;" : "=f"(lo), "=f"(hi) : "l"(x));
    return make_float2(lo, hi);
}
// 16B shared load/store, 32-bit shared-window address (guaranteed LDS/STS.128)
static __device__ __forceinline__ void lds128(u64& a, u64& b, unsigned addr) {
    asm volatile("ld.shared.v2.u64 {%0, %1}, [%2];" : "=l"(a), "=l"(b) : "r"(addr));
}
static __device__ __forceinline__ void sts128(unsigned addr, u64 a, u64 b) {
    asm volatile("st.shared.v2.u64 [%0], {%1, %2};" :: "r"(addr), "l"(a), "l"(b) : "memory");
}

// flag-independent transcendentals (MUFU EX2/RCP based, rel err ~1e-6)
static __device__ __forceinline__ float fast_tanh(float x) {
    float xc = fminf(fmaxf(x, -9.0f), 9.0f);
    float e = __expf(2.0f * xc);
    return (e - 1.0f) * __frcp_rn(e + 1.0f);
}
static __device__ __forceinline__ float fast_sigm(float x) {
    float xc = fminf(fmaxf(x, -30.0f), 30.0f);
    return __frcp_rn(1.0f + __expf(-xc));
}

struct Seg { unsigned off; int K; };   // off = 32-bit shared-window byte address

// ---- single-output GEMM: out[8 rows][256 cols] = epi(sum_segs inT @ W + bias)
// 512 threads, 4-way K-split: g = tid>>7 owns a K-quarter, j = tid&127 a col pair.
template <class Epi>
static __device__ __forceinline__ void gemm256(
    const float* __restrict__ W, int ldW, const float* __restrict__ bias,
    const Seg* segs, int nseg, int Ktot, unsigned red_off, int tid, Epi epi)
{
    const int Kq = Ktot >> 2;
    const int g = tid >> 7, j = tid & 127, n0 = j * 2;
    const int lo = g * Kq, hi = lo + Kq;
    const int ldW2 = ldW >> 1;
    u64 acc[2][4];
    #pragma unroll
    for (int c = 0; c < 2; ++c)
        #pragma unroll
        for (int p = 0; p < 4; ++p) acc[c][p] = 0ull;

    int base = 0;
    for (int s = 0; s < nseg; ++s) {
        int K = segs[s].K;
        int a = lo - base; if (a < 0) a = 0;
        int b = hi - base; if (b > K) b = K;
        if (a < b) {
            const float2* wrow = (const float2*)(W + (size_t)(base + a) * ldW) + (n0 >> 1);
            unsigned ip = segs[s].off + (unsigned)a * SROWB;
            #pragma unroll 8
            for (int k = a; k < b; ++k) {
                float2 wv = __ldg(wrow);
                u64 iax, iay, ibx, iby;
                lds128(iax, iay, ip);
                lds128(ibx, iby, ip + 16);
                u64 w0 = pack2(wv.x), w1 = pack2(wv.y);
                fma2(acc[0][0], iax, w0); fma2(acc[0][1], iay, w0);
                fma2(acc[0][2], ibx, w0); fma2(acc[0][3], iby, w0);
                fma2(acc[1][0], iax, w1); fma2(acc[1][1], iay, w1);
                fma2(acc[1][2], ibx, w1); fma2(acc[1][3], iby, w1);
                wrow += ldW2; ip += SROWB;
            }
        }
        base += K;
    }
    if (g) {
        unsigned wp = red_off + (unsigned)(((g - 1) * 128 + j) * 8) * 8;
        #pragma unroll
        for (int c = 0; c < 2; ++c)
            #pragma unroll
            for (int p = 0; p < 4; p += 2)
                sts128(wp + (unsigned)(c * 4 + p) * 8, acc[c][p], acc[c][p + 1]);
    }
    __syncthreads();
    if (!g) {
        #pragma unroll
        for (int c = 0; c < 2; ++c) {
            float v[8];
            #pragma unroll
            for (int p = 0; p < 4; p += 2) {
                #pragma unroll
                for (int gg = 0; gg < 3; ++gg) {
                    u64 ra, rb;
                    lds128(ra, rb, red_off + (unsigned)((gg * 128 + j) * 8 + c * 4 + p) * 8);
                    add2(acc[c][p], ra); add2(acc[c][p + 1], rb);
                }
            }
            #pragma unroll
            for (int p = 0; p < 4; ++p) {
                float2 f = unpack2(acc[c][p]);
                v[2 * p] = f.x; v[2 * p + 1] = f.y;
            }
            float bn = __ldg(bias + n0 + c);
            #pragma unroll
            for (int r = 0; r < 8; ++r) v[r] += bn;
            epi(n0 + c, v);
        }
    }
    __syncthreads();
}

// ---- dual-output GEMM: one input stream, two weight matrices. Halves the LDS
// traffic and barrier count vs two single passes over the same stream.
template <class Epi>
static __device__ __forceinline__ void gemm256_dual(
    const float* __restrict__ W0, int ld0, const float* __restrict__ b0,
    const float* __restrict__ W1, int ld1, const float* __restrict__ b1,
    const Seg* segs, int nseg, int Ktot, unsigned red_off, int tid, Epi epi)
{
    const int Kq = Ktot >> 2;
    const int g = tid >> 7, j = tid & 127, n0 = j * 2;
    const int lo = g * Kq, hi = lo + Kq;
    const int ld02 = ld0 >> 1, ld12 = ld1 >> 1;
    u64 a0[2][4], a1[2][4];
    #pragma unroll
    for (int c = 0; c < 2; ++c)
        #pragma unroll
        for (int p = 0; p < 4; ++p) { a0[c][p] = 0ull; a1[c][p] = 0ull; }

    int base = 0;
    for (int s = 0; s < nseg; ++s) {
        int K = segs[s].K;
        int a = lo - base; if (a < 0) a = 0;
        int b = hi - base; if (b > K) b = K;
        if (a < b) {
            const float2* w0p = (const float2*)(W0 + (size_t)(base + a) * ld0) + (n0 >> 1);
            const float2* w1p = (const float2*)(W1 + (size_t)(base + a) * ld1) + (n0 >> 1);
            unsigned ip = segs[s].off + (unsigned)a * SROWB;
            #pragma unroll 4
            for (int k = a; k < b; ++k) {
                float2 wv0 = __ldg(w0p);
                float2 wv1 = __ldg(w1p);
                u64 iax, iay, ibx, iby;
                lds128(iax, iay, ip);
                lds128(ibx, iby, ip + 16);
                u64 p00 = pack2(wv0.x), p01 = pack2(wv0.y);
                u64 p10 = pack2(wv1.x), p11 = pack2(wv1.y);
                fma2(a0[0][0], iax, p00); fma2(a0[0][1], iay, p00);
                fma2(a0[0][2], ibx, p00); fma2(a0[0][3], iby, p00);
                fma2(a0[1][0], iax, p01); fma2(a0[1][1], iay, p01);
                fma2(a0[1][2], ibx, p01); fma2(a0[1][3], iby, p01);
                fma2(a1[0][0], iax, p10); fma2(a1[0][1], iay, p10);
                fma2(a1[0][2], ibx, p10); fma2(a1[0][3], iby, p10);
                fma2(a1[1][0], iax, p11); fma2(a1[1][1], iay, p11);
                fma2(a1[1][2], ibx, p11); fma2(a1[1][3], iby, p11);
                w0p += ld02; w1p += ld12; ip += SROWB;
            }
        }
        base += K;
    }
    if (g) {
        unsigned wp = red_off + (unsigned)(((g - 1) * 128 + j) * 16) * 8;
        #pragma unroll
        for (int c = 0; c < 2; ++c)
            #pragma unroll
            for (int p = 0; p < 4; p += 2) {
                sts128(wp + (unsigned)(c * 4 + p) * 8, a0[c][p], a0[c][p + 1]);
                sts128(wp + (unsigned)(8 + c * 4 + p) * 8, a1[c][p], a1[c][p + 1]);
            }
    }
    __syncthreads();
    if (!g) {
        #pragma unroll
        for (int gg = 0; gg < 3; ++gg) {
            unsigned rp = red_off + (unsigned)((gg * 128 + j) * 16) * 8;
            #pragma unroll
            for (int c = 0; c < 2; ++c)
                #pragma unroll
                for (int p = 0; p < 4; p += 2) {
                    u64 ra, rb;
                    lds128(ra, rb, rp + (unsigned)(c * 4 + p) * 8);
                    add2(a0[c][p], ra); add2(a0[c][p + 1], rb);
                    lds128(ra, rb, rp + (unsigned)(8 + c * 4 + p) * 8);
                    add2(a1[c][p], ra); add2(a1[c][p + 1], rb);
                }
        }
        #pragma unroll
        for (int c = 0; c < 2; ++c) {
            float v0[8], v1[8];
            #pragma unroll
            for (int p = 0; p < 4; ++p) {
                float2 f = unpack2(a0[c][p]);
                v0[2 * p] = f.x; v0[2 * p + 1] = f.y;
                f = unpack2(a1[c][p]);
                v1[2 * p] = f.x; v1[2 * p + 1] = f.y;
            }
            float bn0 = __ldg(b0 + n0 + c), bn1 = __ldg(b1 + n0 + c);
            #pragma unroll
            for (int r = 0; r < 8; ++r) { v0[r] += bn0; v1[r] += bn1; }
            epi(n0 + c, v0, v1);
        }
    }
    __syncthreads();
}

// N=64 output head: 1 col/thread, 8-way K split.
template <class Epi>
static __device__ __forceinline__ void gemm64(
    const float* __restrict__ W, int ldW, const float* __restrict__ bias,
    unsigned in_off, int Ktot, unsigned red_off, int tid, Epi epi)
{
    const int Kq = Ktot >> 3;
    const int g = tid >> 6, j = tid & 63;
    u64 acc[4] = {0ull, 0ull, 0ull, 0ull};
    const float* wrow = W + (size_t)(g * Kq) * ldW + j;
    unsigned ip = in_off + (unsigned)(g * Kq) * SROWB;
    #pragma unroll 8
    for (int k = 0; k < Kq; ++k) {
        float wv = __ldg(wrow);
        u64 iax, iay, ibx, iby;
        lds128(iax, iay, ip);
        lds128(ibx, iby, ip + 16);
        u64 w0 = pack2(wv);
        fma2(acc[0], iax, w0); fma2(acc[1], iay, w0);
        fma2(acc[2], ibx, w0); fma2(acc[3], iby, w0);
        wrow += ldW; ip += SROWB;
    }
    if (g) {
        unsigned wp = red_off + (unsigned)(((g - 1) * 64 + j) * 4) * 8;
        sts128(wp, acc[0], acc[1]);
        sts128(wp + 16, acc[2], acc[3]);
    }
    __syncthreads();
    if (!g) {
        #pragma unroll
        for (int gg = 0; gg < 7; ++gg) {
            u64 ra, rb, rc, rd;
            unsigned rp = red_off + (unsigned)((gg * 64 + j) * 4) * 8;
            lds128(ra, rb, rp);
            lds128(rc, rd, rp + 16);
            add2(acc[0], ra); add2(acc[1], rb);
            add2(acc[2], rc); add2(acc[3], rd);
        }
        float v[8];
        #pragma unroll
        for (int p = 0; p < 4; ++p) {
            float2 f = unpack2(acc[p]);
            v[2 * p] = f.x; v[2 * p + 1] = f.y;
        }
        float bn = __ldg(bias + j);
        #pragma unroll
        for (int r = 0; r < 8; ++r) v[r] += bn;
        epi(j, v);
    }
    __syncthreads();
}

// ---- SMEM layout (float offsets) ----
#define O_HI    0
#define O_STD   3072
#define O_ODE   6144
#define O_T1A   9216
#define O_T1B   12288
#define O_U     15360
#define O_ODER  18432
#define O_STDR  21504
#define O_X     24576   // 64*SROW = 768
#define O_RED   25344   // 6144 u64 = 12288 floats (48KB)
#define O_TIME  37632   // float xtime[200]
#define O_INT   37832   // int invx[200], invy[200]
#define SMEM_BYTES ((37832 + 400) * 4)

__global__ void __launch_bounds__(NTHR, 1) recur_kernel(
    const float* __restrict__ xd, const float* __restrict__ xm,
    const float* __restrict__ xt,
    const int* __restrict__ xti, const int* __restrict__ yti,
    const float* __restrict__ ugw1, const float* __restrict__ ugb1,
    const float* __restrict__ ugw2, const float* __restrict__ ugb2,
    const float* __restrict__ rgw1, const float* __restrict__ rgb1,
    const float* __restrict__ rgw2, const float* __restrict__ rgb2,
    const float* __restrict__ nsw1, const float* __restrict__ nsb1,
    const float* __restrict__ nsw2, const float* __restrict__ nsb2,
    const float* __restrict__ ow1, const float* __restrict__ ob1,
    const float* __restrict__ ow2, const float* __restrict__ ob2,
    const float* __restrict__ fw1, const float* __restrict__ fb1,
    const float* __restrict__ fw2, const float* __restrict__ fb2,
    float* __restrict__ out)
{
    extern __shared__ float sm[];
    const unsigned SB = (unsigned)__cvta_generic_to_shared(sm);
    float* s_hi   = sm + O_HI;
    float* s_std  = sm + O_STD;
    float* s_ode  = sm + O_ODE;
    float* s_t1a  = sm + O_T1A;
    float* s_t1b  = sm + O_T1B;
    float* s_u    = sm + O_U;
    float* s_oder = sm + O_ODER;
    float* s_stdr = sm + O_STDR;
    float* s_x    = sm + O_X;
    float* s_time = sm + O_TIME;
    int*   s_invx = (int*)(sm + O_INT);
    int*   s_invy = s_invx + 200;

    const unsigned u_hi   = SB + O_HI * 4;
    const unsigned u_ode  = SB + O_ODE * 4;
    const unsigned u_std  = SB + O_STD * 4;
    const unsigned u_t1a  = SB + O_T1A * 4;
    const unsigned u_t1b  = SB + O_T1B * 4;
    const unsigned u_oder = SB + O_ODER * 4;
    const unsigned u_stdr = SB + O_STDR * 4;
    const unsigned u_x    = SB + O_X * 4;
    const unsigned u_red  = SB + O_RED * 4;

    const int tid = threadIdx.x;
    const int b0 = blockIdx.x * 8;

    for (int i = tid; i < 3072; i += NTHR) { s_hi[i] = 0.0f; s_std[i] = 0.0f; }
    if (tid < 200) { s_invx[tid] = -1; s_invy[tid] = -1; s_time[tid] = __ldg(xt + tid); }
    __syncthreads();
    if (tid < 190) s_invx[xti[tid]] = tid;
    if (tid < 50)  s_invy[yti[tid]] = tid;
    __syncthreads();

    const float xlast = s_time[199];

    auto epiTanhT1A = [&](int n, const float* v) {
        #pragma unroll
        for (int r = 0; r < 8; ++r) s_t1a[n * SROW + r] = fast_tanh(v[r]);
    };

    for (int t = 0; t < 200; ++t) {
        // scatter this step's observation slot into s_x (zeros if unobserved)
        {
            int jx = s_invx[t];
            int r = tid >> 6, c = tid & 63;   // 512 threads cover 8x64
            float v = 0.0f;
            if (jx >= 0) {
                size_t off = ((size_t)(b0 + r) * 190 + jx) * 64 + c;
                v = __ldg(xd + off) * __ldg(xm + off);
            }
            s_x[c * SROW + r] = v;   // first read (ug1rg1) is 2+ barriers later
        }
        // dt exactly as the reference's carried (prev_ti, ti) produce it
        float dt;
        if (t == 0)      dt = -0.01f;
        else if (t == 1) dt = xlast - s_time[0];
        else             dt = s_time[t - 2] - s_time[t - 1];

        Seg sH[1]  = {{u_hi, 256}};
        Seg sTA[1] = {{u_t1a, 256}};
        Seg sTB[1] = {{u_t1b, 256}};
        Seg sYC[3] = {{u_ode, 256}, {u_std, 256}, {u_x, 64}};
        Seg sCC[3] = {{u_oder, 256}, {u_stdr, 256}, {u_x, 64}};

        // f = MLP(hi); hi_ode = hi + f*dt
        gemm256(fw1, 256, fb1, sH, 1, 256, u_red, tid, epiTanhT1A);
        gemm256(fw2, 256, fb2, sTA, 1, 256, u_red, tid,
            [&](int n, const float* v) {
                #pragma unroll
                for (int r = 0; r < 8; ++r)
                    s_ode[n * SROW + r] = s_hi[n * SROW + r] + v[r] * dt;
            });
        // fused gate hidden layers: one yc stream, two weight sets
        gemm256_dual(ugw1, 256, ugb1, rgw1, 256, rgb1, sYC, 3, 576, u_red, tid,
            [&](int n, const float* v0, const float* v1) {
                #pragma unroll
                for (int r = 0; r < 8; ++r) {
                    s_t1a[n * SROW + r] = fast_tanh(v0[r]);
                    s_t1b[n * SROW + r] = fast_tanh(v1[r]);
                }
            });
        // u = sigmoid(. @ ugw2)
        gemm256(ugw2, 256, ugb2, sTA, 1, 256, u_red, tid,
            [&](int n, const float* v) {
                #pragma unroll
                for (int r = 0; r < 8; ++r) s_u[n * SROW + r] = fast_sigm(v[r]);
            });
        // r = sigmoid(. @ rgw2); fold the cc mult into this epilogue
        gemm256(rgw2, 256, rgb2, sTB, 1, 256, u_red, tid,
            [&](int n, const float* v) {
                #pragma unroll
                for (int r = 0; r < 8; ++r) {
                    float rr = fast_sigm(v[r]);
                    s_oder[n * SROW + r] = s_ode[n * SROW + r] * rr;
                    s_stdr[n * SROW + r] = s_std[n * SROW + r] * rr;
                }
            });
        // ns hidden
        gemm256(nsw1, 256, nsb1, sCC, 3, 576, u_red, tid, epiTanhT1A);
        // fused ns output halves: nsw2 [256][512] cols [0,256) and [256,512)
        gemm256_dual(nsw2, 512, nsb2, nsw2 + 256, 512, nsb2 + 256,
                     sTA, 1, 256, u_red, tid,
            [&](int n, const float* v0, const float* v1) {
                #pragma unroll
                for (int r = 0; r < 8; ++r) {
                    float u = s_u[n * SROW + r];
                    float ode = s_ode[n * SROW + r];
                    float sd  = s_std[n * SROW + r];
                    s_hi[n * SROW + r] = (1.0f - u) * v0[r] + u * ode;
                    s_std[n * SROW + r] =
                        fabsf((1.0f - u) * fabsf(v1[r]) + u * sd);
                }
            });
        // output head only on the 50 sampled steps
        int q = s_invy[t];
        if (q >= 0) {
            Seg sHn[1] = {{u_hi, 256}};
            gemm256(ow1, 256, ob1, sHn, 1, 256, u_red, tid, epiTanhT1A);
            gemm64(ow2, 64, ob2, u_t1a, 256, u_red, tid,
                [&](int n, const float* v) {
                    #pragma unroll
                    for (int r = 0; r < 8; ++r)
                        out[((size_t)(b0 + r) * 50 + q) * 64 + n] = v[r];
                });
        }
    }
}

extern "C" void kernel_launch(void* const* d_in, const int* in_sizes, int n_in,
                              void* d_out, int out_size) {
    (void)in_sizes; (void)n_in; (void)out_size;
    const float* xd   = (const float*)d_in[0];
    const float* xm   = (const float*)d_in[1];
    const float* xt   = (const float*)d_in[2];
    const int*   xti  = (const int*)d_in[3];
    const int*   yti  = (const int*)d_in[4];
    const float* ugw1 = (const float*)d_in[5];
    const float* ugb1 = (const float*)d_in[6];
    const float* ugw2 = (const float*)d_in[7];
    const float* ugb2 = (const float*)d_in[8];
    const float* rgw1 = (const float*)d_in[9];
    const float* rgb1 = (const float*)d_in[10];
    const float* rgw2 = (const float*)d_in[11];
    const float* rgb2 = (const float*)d_in[12];
    const float* nsw1 = (const float*)d_in[13];
    const float* nsb1 = (const float*)d_in[14];
    const float* nsw2 = (const float*)d_in[15];
    const float* nsb2 = (const float*)d_in[16];
    const float* ow1  = (const float*)d_in[17];
    const float* ob1  = (const float*)d_in[18];
    const float* ow2  = (const float*)d_in[19];
    const float* ob2  = (const float*)d_in[20];
    const float* fw1  = (const float*)d_in[21];
    const float* fb1  = (const float*)d_in[22];
    const float* fw2  = (const float*)d_in[23];
    const float* fb2  = (const float*)d_in[24];

    cudaFuncSetAttribute(recur_kernel,
                         cudaFuncAttributeMaxDynamicSharedMemorySize, SMEM_BYTES);
    recur_kernel<<<128, NTHR, SMEM_BYTES>>>(
        xd, xm, xt, xti, yti,
        ugw1, ugb1, ugw2, ugb2,
        rgw1, rgb1, rgw2, rgb2,
        nsw1, nsb1, nsw2, nsb2,
        ow1, ob1, ow2, ob2,
        fw1, fb1, fw2, fb2,
        (float*)d_out);
}